// round 15
// baseline (speedup 1.0000x reference)
#include <cuda_runtime.h>
#include <cuda_fp16.h>
#include <cstdint>

// Problem constants
#define H 16
#define D 64
#define S 1024
#define START_FRAME 9728
#define NKV 8192
#define CACHE_OFF 2560
#define SPLIT 7168
#define BM 128
#define BN 64
#define NSPLIT 10                 // 128 tiles = 8 splits x 13 + 2 splits x 12
#define KS 72                     // smem row stride in halves (144B, conflict-free)

// smem: 4 stages of (K [64][72] | V [64][72]) = 73728 B. Q staged into stage 0.
#define TILE_H    4608            // 64*72
#define STAGE_H   (2 * TILE_H)    // 9216 halves
#define SM_HALVES (4 * STAGE_H)   // 36864 halves = 73728 B

// Scratch
__device__ __align__(16) __half g_qh[(size_t)H * S * D];    // roped Q fp16 [h][s][d]
__device__ __align__(16) __half g_kh[(size_t)H * NKV * D];  // window K fp16 [h][key][d]
__device__ __align__(16) __half g_vh[(size_t)H * NKV * D];  // window V fp16 [h][key][d]
__device__ __align__(16) __half g_po[(size_t)NSPLIT * S * H * D];  // partial O (fp16)
__device__ __align__(16) float  g_l[NSPLIT * S * H];        // partial denom (fp32)

// ---------------------------------------------------------------------------
// Helpers
// ---------------------------------------------------------------------------
__device__ __forceinline__ uint32_t cvt_f16x2(float hi, float lo) {
    uint32_t r;
    asm("cvt.rn.f16x2.f32 %0, %1, %2;" : "=r"(r) : "f"(hi), "f"(lo));
    return r;
}
__device__ __forceinline__ uint32_t ex2_f16x2(uint32_t x) {
    uint32_t y;
    asm("ex2.approx.f16x2 %0, %1;" : "=r"(y) : "r"(x));
    return y;
}
__device__ __forceinline__ void mma_f16(float* c, const uint32_t* a, uint32_t b0, uint32_t b1) {
    asm volatile(
        "mma.sync.aligned.m16n8k16.row.col.f32.f16.f16.f32 "
        "{%0,%1,%2,%3}, {%4,%5,%6,%7}, {%8,%9}, {%0,%1,%2,%3};\n"
        : "+f"(c[0]), "+f"(c[1]), "+f"(c[2]), "+f"(c[3])
        : "r"(a[0]), "r"(a[1]), "r"(a[2]), "r"(a[3]), "r"(b0), "r"(b1));
}
__device__ __forceinline__ void ldsm_x4(uint32_t addr, uint32_t& r0, uint32_t& r1,
                                        uint32_t& r2, uint32_t& r3) {
    asm volatile("ldmatrix.sync.aligned.m8n8.x4.shared.b16 {%0,%1,%2,%3}, [%4];"
                 : "=r"(r0), "=r"(r1), "=r"(r2), "=r"(r3) : "r"(addr));
}
__device__ __forceinline__ void ldsm_x4_t(uint32_t addr, uint32_t& r0, uint32_t& r1,
                                          uint32_t& r2, uint32_t& r3) {
    asm volatile("ldmatrix.sync.aligned.m8n8.x4.trans.shared.b16 {%0,%1,%2,%3}, [%4];"
                 : "=r"(r0), "=r"(r1), "=r"(r2), "=r"(r3) : "r"(addr));
}
__device__ __forceinline__ void ldsm_x2_t(uint32_t addr, uint32_t& r0, uint32_t& r1) {
    asm volatile("ldmatrix.sync.aligned.m8n8.x2.trans.shared.b16 {%0,%1}, [%2];"
                 : "=r"(r0), "=r"(r1) : "r"(addr));
}
__device__ __forceinline__ void cp16(uint32_t smem_addr, const void* gptr) {
    asm volatile("cp.async.cg.shared.global [%0], [%1], 16;"
                 :: "r"(smem_addr), "l"(gptr));
}
__device__ __forceinline__ void stg_cs_u32(void* gptr, uint32_t v) {
    asm volatile("st.global.cs.b32 [%0], %1;" :: "l"(gptr), "r"(v) : "memory");
}
#define CP_COMMIT() asm volatile("cp.async.commit_group;" ::: "memory")
#define CP_WAIT(N)  asm volatile("cp.async.wait_group %0;" :: "n"(N) : "memory")

// ---------------------------------------------------------------------------
// Fused prep, 8 elements (uint4 out) per thread (unchanged, at traffic floor).
// ---------------------------------------------------------------------------
#define ROPE_ITEMS (S * H * 8)
#define CONV_ITEMS (SPLIT * H * 8)

__global__ void prep_fused(const float* __restrict__ q, const float* __restrict__ k,
                           const float* __restrict__ v,
                           const float* __restrict__ cache_k,
                           const float* __restrict__ cache_v,
                           const float* __restrict__ fc, const float* __restrict__ fs) {
    const float SC = 1.4426950408889634f * 0.125f;
    int idx = blockIdx.x * blockDim.x + threadIdx.x;
    if (idx < ROPE_ITEMS) {
        int c8 = (idx & 7) << 3;
        int h  = (idx >> 3) & 15;
        int s  = idx >> 7;
        int pos = START_FRAME + s;
        float4 fc0 = *(const float4*)&fc[pos * 64 + c8];
        float4 fc1 = *(const float4*)&fc[pos * 64 + c8 + 4];
        float4 fs0 = *(const float4*)&fs[pos * 64 + c8];
        float4 fs1 = *(const float4*)&fs[pos * 64 + c8 + 4];
        int base = (s * H + h) * D + c8;
        float4 q0 = *(const float4*)&q[base];
        float4 q1 = *(const float4*)&q[base + 4];
        float4 k0 = *(const float4*)&k[base];
        float4 k1 = *(const float4*)&k[base + 4];
        float4 v0 = *(const float4*)&v[base];
        float4 v1 = *(const float4*)&v[base + 4];

        uint4 qo, ko, vo;
        qo.x = cvt_f16x2((q0.y * fc0.x + q0.x * fs0.x) * SC, (q0.x * fc0.x - q0.y * fs0.x) * SC);
        qo.y = cvt_f16x2((q0.w * fc0.z + q0.z * fs0.z) * SC, (q0.z * fc0.z - q0.w * fs0.z) * SC);
        qo.z = cvt_f16x2((q1.y * fc1.x + q1.x * fs1.x) * SC, (q1.x * fc1.x - q1.y * fs1.x) * SC);
        qo.w = cvt_f16x2((q1.w * fc1.z + q1.z * fs1.z) * SC, (q1.z * fc1.z - q1.w * fs1.z) * SC);
        ko.x = cvt_f16x2(k0.y * fc0.x + k0.x * fs0.x, k0.x * fc0.x - k0.y * fs0.x);
        ko.y = cvt_f16x2(k0.w * fc0.z + k0.z * fs0.z, k0.z * fc0.z - k0.w * fs0.z);
        ko.z = cvt_f16x2(k1.y * fc1.x + k1.x * fs1.x, k1.x * fc1.x - k1.y * fs1.x);
        ko.w = cvt_f16x2(k1.w * fc1.z + k1.z * fs1.z, k1.z * fc1.z - k1.w * fs1.z);
        vo.x = cvt_f16x2(v0.y, v0.x);
        vo.y = cvt_f16x2(v0.w, v0.z);
        vo.z = cvt_f16x2(v1.y, v1.x);
        vo.w = cvt_f16x2(v1.w, v1.z);

        *(uint4*)&g_qh[((size_t)h * S + s) * D + c8] = qo;
        size_t dst = ((size_t)h * NKV + SPLIT + s) * D + c8;
        *(uint4*)&g_kh[dst] = ko;
        *(uint4*)&g_vh[dst] = vo;
    } else {
        int i8 = idx - ROPE_ITEMS;
        if (i8 >= CONV_ITEMS) return;
        int c8 = (i8 & 7) << 3;
        int h  = (i8 >> 3) & 15;
        int j  = i8 >> 7;
        size_t src = (size_t)(CACHE_OFF + j) * (H * D) + h * D + c8;
        float4 k0 = *(const float4*)&cache_k[src];
        float4 k1 = *(const float4*)&cache_k[src + 4];
        float4 v0 = *(const float4*)&cache_v[src];
        float4 v1 = *(const float4*)&cache_v[src + 4];
        uint4 ko = make_uint4(cvt_f16x2(k0.y, k0.x), cvt_f16x2(k0.w, k0.z),
                              cvt_f16x2(k1.y, k1.x), cvt_f16x2(k1.w, k1.z));
        uint4 vo = make_uint4(cvt_f16x2(v0.y, v0.x), cvt_f16x2(v0.w, v0.z),
                              cvt_f16x2(v1.y, v1.x), cvt_f16x2(v1.w, v1.z));
        size_t dst = ((size_t)h * NKV + j) * D + c8;
        *(uint4*)&g_kh[dst] = ko;
        *(uint4*)&g_vh[dst] = vo;
    }
}

// ---------------------------------------------------------------------------
// Flash attention (round-12 body, NSPLIT=10 slot-quantization fix):
// fp16 mma m16n8k16, ldmatrix B (+.trans V), 4-stage ring cp.async (depth-3),
// fused per-16-key block, ones-column L MMA, f16x2 softmax, async Q prologue.
// grid = (8, 16, 10) = 1280 CTAs, block = 128 (4 warps x 32 q-rows), 3 CTAs/SM.
// Splits 0-7 cover 13 tiles, splits 8-9 cover 12 (128 total).
// ---------------------------------------------------------------------------
__device__ __forceinline__ void prefetch_tile(uint32_t kbase, uint32_t vbase,
                                              int tid, int h, int kt) {
    const char* ksrc = (const char*)&g_kh[((size_t)h * NKV + (size_t)kt * BN) * D];
    const char* vsrc = (const char*)&g_vh[((size_t)h * NKV + (size_t)kt * BN) * D];
    #pragma unroll
    for (int g = 0; g < 4; g++) {
        int idx = tid + g * 128;
        int r = idx >> 3, c = idx & 7;
        uint32_t off = (uint32_t)(r * KS + c * 8) * 2;
        cp16(kbase + off, ksrc + (size_t)idx * 16);
        cp16(vbase + off, vsrc + (size_t)idx * 16);
    }
}

__global__ __launch_bounds__(128, 3) void attn_fp16() {
    extern __shared__ __align__(16) __half smem[];

    const int h     = blockIdx.y;
    const int q0    = blockIdx.x * BM;
    const int split = blockIdx.z;
    const int tid   = threadIdx.x;
    const int warp  = tid >> 5;
    const int lane  = tid & 31;
    const int gid   = lane >> 2;
    const int tig   = lane & 3;
    // uneven split map: 128 tiles = 8x13 + 2x12
    const int kt0 = split * 12 + min(split, 8);
    const int nt  = 12 + (split < 8 ? 1 : 0);

    const uint32_t sb = (uint32_t)__cvta_generic_to_shared(smem);
    uint32_t kaddr[4], vaddr[4];
    #pragma unroll
    for (int t = 0; t < 4; t++) {
        kaddr[t] = sb + (uint32_t)(t * STAGE_H) * 2u;
        vaddr[t] = kaddr[t] + (uint32_t)TILE_H * 2u;
    }

    const uint32_t loffB =
        (uint32_t)((((lane >> 4) & 1) * 8 + (lane & 7)) * KS * 2 + ((lane >> 3) & 1) * 16);
    const uint32_t loffA =
        (uint32_t)((lane & 15) * KS * 2 + ((lane >> 4) & 1) * 16);
    const uint32_t loffBV =
        (uint32_t)((((lane >> 3) & 1) * 8 + (lane & 7)) * KS * 2 + ((lane >> 4) & 1) * 16);
    const uint32_t loffLV =
        (uint32_t)((((lane >> 3) & 1) * 8 + (lane & 7)) * KS * 2 + 128);

    // prologue: async Q into stage 0 (halves 0-63 of 128 rows)
    {
        const char* qsrc = (const char*)&g_qh[((size_t)h * S + q0) * D];
        #pragma unroll
        for (int g = 0; g < 8; g++) {
            int idx = tid + g * 128;
            int r = idx >> 3, c = idx & 7;
            cp16(sb + (uint32_t)(r * KS + c * 8) * 2, qsrc + (size_t)idx * 16);
        }
        CP_COMMIT();
    }
    // tiles 0,1,2 into stages 1,2,3 (tile j lives in stage (j+1)&3); nt>=12
    prefetch_tile(kaddr[1], vaddr[1], tid, h, kt0);     CP_COMMIT();
    prefetch_tile(kaddr[2], vaddr[2], tid, h, kt0 + 1); CP_COMMIT();
    prefetch_tile(kaddr[3], vaddr[3], tid, h, kt0 + 2); CP_COMMIT();

    // ones-column (dim 64) / zeros (65-71) in all 4 V areas (never touched
    // by cp.async, which writes halves 0-63 only)
    {
        const __half one = __float2half(1.0f), zero = __float2half(0.0f);
        for (int i = tid; i < 4 * 64 * 8; i += 128) {
            int t = i >> 9, rem = i & 511;
            int key = rem >> 3, dd = 64 + (rem & 7);
            smem[t * STAGE_H + TILE_H + key * KS + dd] = (dd == 64) ? one : zero;
        }
    }

    CP_WAIT(3);
    __syncthreads();

    uint32_t qa[2][4][4];
    #pragma unroll
    for (int mt = 0; mt < 2; mt++) {
        uint32_t rowbase = sb + (uint32_t)((warp * 32 + mt * 16) * KS * 2) + loffA;
        #pragma unroll
        for (int kk = 0; kk < 4; kk++)
            ldsm_x4(rowbase + (uint32_t)(kk * 32),
                    qa[mt][kk][0], qa[mt][kk][1], qa[mt][kk][2], qa[mt][kk][3]);
    }

    float o[2][8][4];
    #pragma unroll
    for (int mt = 0; mt < 2; mt++)
        #pragma unroll
        for (int nn = 0; nn < 8; nn++)
            o[mt][nn][0] = o[mt][nn][1] = o[mt][nn][2] = o[mt][nn][3] = 0.f;
    float oL[2][4];
    #pragma unroll
    for (int mt = 0; mt < 2; mt++)
        oL[mt][0] = oL[mt][1] = oL[mt][2] = oL[mt][3] = 0.f;

    for (int j = 0; j < nt; j++) {
        const int cs = (j + 1) & 3;

        if (j + 2 < nt)      { CP_WAIT(2); }
        else if (j + 1 < nt) { CP_WAIT(1); }
        else                 { CP_WAIT(0); }
        __syncthreads();   // tile j visible; stage (j)&3 consumed (iter j-1);
                           // at j==0 also orders qa loads before stage-0 reuse

        if (j + 3 < nt) {
            prefetch_tile(kaddr[j & 3], vaddr[j & 3], tid, h, kt0 + j + 3);
            CP_COMMIT();
        }

        // ---- fused per-16-key block: MMA1 -> softmax -> L + MMA2 ----
        #pragma unroll
        for (int kb = 0; kb < 4; kb++) {
            float sacc[2][2][4];
            #pragma unroll
            for (int mt = 0; mt < 2; mt++)
                #pragma unroll
                for (int nn = 0; nn < 2; nn++)
                    sacc[mt][nn][0] = sacc[mt][nn][1] = sacc[mt][nn][2] = sacc[mt][nn][3] = 0.f;
            #pragma unroll
            for (int kd = 0; kd < 4; kd++) {
                uint32_t b0, b1, b2, b3;
                ldsm_x4(kaddr[cs] + loffB + (uint32_t)(kb * 16 * KS * 2 + kd * 32),
                        b0, b1, b2, b3);
                mma_f16(sacc[0][0], qa[0][kd], b0, b1);
                mma_f16(sacc[0][1], qa[0][kd], b2, b3);
                mma_f16(sacc[1][0], qa[1][kd], b0, b1);
                mma_f16(sacc[1][1], qa[1][kd], b2, b3);
            }
            uint32_t pa[2][4];
            #pragma unroll
            for (int mt = 0; mt < 2; mt++) {
                pa[mt][0] = ex2_f16x2(cvt_f16x2(sacc[mt][0][1], sacc[mt][0][0]));
                pa[mt][1] = ex2_f16x2(cvt_f16x2(sacc[mt][0][3], sacc[mt][0][2]));
                pa[mt][2] = ex2_f16x2(cvt_f16x2(sacc[mt][1][1], sacc[mt][1][0]));
                pa[mt][3] = ex2_f16x2(cvt_f16x2(sacc[mt][1][3], sacc[mt][1][2]));
            }
            {
                uint32_t bL0, bL1;
                ldsm_x2_t(vaddr[cs] + loffLV + (uint32_t)(kb * 16 * KS * 2), bL0, bL1);
                mma_f16(oL[0], pa[0], bL0, bL1);
                mma_f16(oL[1], pa[1], bL0, bL1);
            }
            #pragma unroll
            for (int nnp = 0; nnp < 4; nnp++) {
                uint32_t b0, b1, b2, b3;
                ldsm_x4_t(vaddr[cs] + loffBV + (uint32_t)(kb * 16 * KS * 2 + nnp * 32),
                          b0, b1, b2, b3);
                mma_f16(o[0][2 * nnp],     pa[0], b0, b1);
                mma_f16(o[0][2 * nnp + 1], pa[0], b2, b3);
                mma_f16(o[1][2 * nnp],     pa[1], b0, b1);
                mma_f16(o[1][2 * nnp + 1], pa[1], b2, b3);
            }
        }
    }

    // epilogue: fp16 partial O via streaming stores, fp32 L (ones-column col 64)
    #pragma unroll
    for (int mt = 0; mt < 2; mt++) {
        int r = q0 + warp * 32 + mt * 16 + gid;
        size_t b0 = ((size_t)split * S + r) * (H * D) + h * 64;
        size_t b1 = ((size_t)split * S + r + 8) * (H * D) + h * 64;
        #pragma unroll
        for (int nn = 0; nn < 8; nn++) {
            stg_cs_u32(&g_po[b0 + nn * 8 + 2 * tig], cvt_f16x2(o[mt][nn][1], o[mt][nn][0]));
            stg_cs_u32(&g_po[b1 + nn * 8 + 2 * tig], cvt_f16x2(o[mt][nn][3], o[mt][nn][2]));
        }
        if (tig == 0) {
            g_l[(size_t)split * (S * H) + (size_t)r * H + h]       = oL[mt][0];
            g_l[(size_t)split * (S * H) + (size_t)(r + 8) * H + h] = oL[mt][2];
        }
    }
}

// ---------------------------------------------------------------------------
// Merge splits: 4 outputs per thread.
// ---------------------------------------------------------------------------
__global__ __launch_bounds__(256) void reduce_kernel(float* __restrict__ out) {
    int t = blockIdx.x * blockDim.x + threadIdx.x;   // S*H*D/4 threads
    if (t >= S * H * D / 4) return;
    int idx = t * 4;
    int h = (idx >> 6) & 15;
    int s = idx >> 10;
    int mlb = s * H + h;

    float den = 0.f;
    #pragma unroll
    for (int i = 0; i < NSPLIT; i++)
        den += g_l[(size_t)i * (S * H) + mlb];

    float acc0 = 0.f, acc1 = 0.f, acc2 = 0.f, acc3 = 0.f;
    #pragma unroll
    for (int i = 0; i < NSPLIT; i++) {
        uint2 pk = *(const uint2*)&g_po[(size_t)i * (S * H * D) + idx];
        float2 a0 = __half22float2(*(const __half2*)&pk.x);
        float2 a1 = __half22float2(*(const __half2*)&pk.y);
        acc0 += a0.x; acc1 += a0.y; acc2 += a1.x; acc3 += a1.y;
    }
    float r = 1.f / den;
    *(float4*)&out[idx] = make_float4(acc0 * r, acc1 * r, acc2 * r, acc3 * r);
}

// ---------------------------------------------------------------------------
extern "C" void kernel_launch(void* const* d_in, const int* in_sizes, int n_in,
                              void* d_out, int out_size) {
    const float* q  = (const float*)d_in[0];
    const float* k  = (const float*)d_in[1];
    const float* v  = (const float*)d_in[2];
    const float* ck = (const float*)d_in[3];
    const float* cv = (const float*)d_in[4];
    const float* fc = (const float*)d_in[5];
    const float* fs = (const float*)d_in[6];
    float* out = (float*)d_out;
    (void)in_sizes; (void)n_in; (void)out_size;

    int prep_items = ROPE_ITEMS + CONV_ITEMS;
    prep_fused<<<(prep_items + 255) / 256, 256>>>(q, k, v, ck, cv, fc, fs);

    cudaFuncSetAttribute(attn_fp16, cudaFuncAttributeMaxDynamicSharedMemorySize,
                         SM_HALVES * 2);
    dim3 grid(S / BM, H, NSPLIT);
    attn_fp16<<<grid, 128, SM_HALVES * 2>>>();

    reduce_kernel<<<(S * H * D / 4 + 255) / 256, 256>>>(out);
}

// round 16
// speedup vs baseline: 1.0531x; 1.0531x over previous
#include <cuda_runtime.h>
#include <cuda_fp16.h>
#include <cstdint>

// Problem constants
#define H 16
#define D 64
#define S 1024
#define START_FRAME 9728
#define NKV 8192
#define CACHE_OFF 2560
#define SPLIT 7168
#define BM 128
#define BN 64
#define NSPLIT 8
#define TPT (NKV / BN / NSPLIT)   // 16 kv tiles per CTA
#define KS 72                     // smem row stride in halves (144B, conflict-free)

// smem: 4 stages of (K [64][72] | V [64][72]) = 73728 B. Q staged into stage 0.
#define TILE_H    4608            // 64*72
#define STAGE_H   (2 * TILE_H)    // 9216 halves
#define SM_HALVES (4 * STAGE_H)   // 36864 halves = 73728 B

// Scratch
__device__ __align__(16) __half g_qh[(size_t)H * S * D];    // roped Q fp16 [h][s][d]
__device__ __align__(16) __half g_kh[(size_t)H * NKV * D];  // window K fp16 [h][key][d]
__device__ __align__(16) __half g_vh[(size_t)H * NKV * D];  // window V fp16 [h][key][d]
__device__ __align__(16) __half g_po[(size_t)NSPLIT * S * H * D];  // partial O (fp16)
__device__ __align__(16) float  g_l[NSPLIT * S * H];        // partial denom (fp32)

// ---------------------------------------------------------------------------
// Helpers
// ---------------------------------------------------------------------------
__device__ __forceinline__ uint32_t cvt_f16x2(float hi, float lo) {
    uint32_t r;
    asm("cvt.rn.f16x2.f32 %0, %1, %2;" : "=r"(r) : "f"(hi), "f"(lo));
    return r;
}
__device__ __forceinline__ uint32_t ex2_f16x2(uint32_t x) {
    uint32_t y;
    asm("ex2.approx.f16x2 %0, %1;" : "=r"(y) : "r"(x));
    return y;
}
__device__ __forceinline__ void mma_f16(float* c, const uint32_t* a, uint32_t b0, uint32_t b1) {
    asm volatile(
        "mma.sync.aligned.m16n8k16.row.col.f32.f16.f16.f32 "
        "{%0,%1,%2,%3}, {%4,%5,%6,%7}, {%8,%9}, {%0,%1,%2,%3};\n"
        : "+f"(c[0]), "+f"(c[1]), "+f"(c[2]), "+f"(c[3])
        : "r"(a[0]), "r"(a[1]), "r"(a[2]), "r"(a[3]), "r"(b0), "r"(b1));
}
__device__ __forceinline__ void ldsm_x4(uint32_t addr, uint32_t& r0, uint32_t& r1,
                                        uint32_t& r2, uint32_t& r3) {
    asm volatile("ldmatrix.sync.aligned.m8n8.x4.shared.b16 {%0,%1,%2,%3}, [%4];"
                 : "=r"(r0), "=r"(r1), "=r"(r2), "=r"(r3) : "r"(addr));
}
__device__ __forceinline__ void ldsm_x4_t(uint32_t addr, uint32_t& r0, uint32_t& r1,
                                          uint32_t& r2, uint32_t& r3) {
    asm volatile("ldmatrix.sync.aligned.m8n8.x4.trans.shared.b16 {%0,%1,%2,%3}, [%4];"
                 : "=r"(r0), "=r"(r1), "=r"(r2), "=r"(r3) : "r"(addr));
}
__device__ __forceinline__ void ldsm_x2_t(uint32_t addr, uint32_t& r0, uint32_t& r1) {
    asm volatile("ldmatrix.sync.aligned.m8n8.x2.trans.shared.b16 {%0,%1}, [%2];"
                 : "=r"(r0), "=r"(r1) : "r"(addr));
}
__device__ __forceinline__ void cp16(uint32_t smem_addr, const void* gptr) {
    asm volatile("cp.async.cg.shared.global [%0], [%1], 16;"
                 :: "r"(smem_addr), "l"(gptr));
}
__device__ __forceinline__ void stg_cs_u32(void* gptr, uint32_t v) {
    asm volatile("st.global.cs.b32 [%0], %1;" :: "l"(gptr), "r"(v) : "memory");
}
#define CP_COMMIT() asm volatile("cp.async.commit_group;" ::: "memory")
#define CP_WAIT(N)  asm volatile("cp.async.wait_group %0;" :: "n"(N) : "memory")

// ---------------------------------------------------------------------------
// Fused prep, 2-way ILP: each thread handles TWO independent 8-dim groups
// (dims c8 and c8+32 of the same row) -> doubled memory-level parallelism.
// items [0, ROPE_ITEMS): RoPE Q->g_qh (scaled fp16), new K/V -> [SPLIT+s]
// items [ROPE_ITEMS, +CONV_ITEMS): rolled cache K/V -> [0..SPLIT)
// ---------------------------------------------------------------------------
#define ROPE_ITEMS (S * H * 4)
#define CONV_ITEMS (SPLIT * H * 4)

__device__ __forceinline__ void rope_pack8(const float* __restrict__ src,
                                           const float* __restrict__ fcp,
                                           const float* __restrict__ fsp,
                                           float scale, uint4& out) {
    float4 a0 = *(const float4*)src;
    float4 a1 = *(const float4*)(src + 4);
    float4 c0 = *(const float4*)fcp;
    float4 c1 = *(const float4*)(fcp + 4);
    float4 s0 = *(const float4*)fsp;
    float4 s1 = *(const float4*)(fsp + 4);
    out.x = cvt_f16x2((a0.y * c0.x + a0.x * s0.x) * scale, (a0.x * c0.x - a0.y * s0.x) * scale);
    out.y = cvt_f16x2((a0.w * c0.z + a0.z * s0.z) * scale, (a0.z * c0.z - a0.w * s0.z) * scale);
    out.z = cvt_f16x2((a1.y * c1.x + a1.x * s1.x) * scale, (a1.x * c1.x - a1.y * s1.x) * scale);
    out.w = cvt_f16x2((a1.w * c1.z + a1.z * s1.z) * scale, (a1.z * c1.z - a1.w * s1.z) * scale);
}
__device__ __forceinline__ void conv_pack8(const float* __restrict__ src, uint4& out) {
    float4 a0 = *(const float4*)src;
    float4 a1 = *(const float4*)(src + 4);
    out = make_uint4(cvt_f16x2(a0.y, a0.x), cvt_f16x2(a0.w, a0.z),
                     cvt_f16x2(a1.y, a1.x), cvt_f16x2(a1.w, a1.z));
}

__global__ void prep_fused(const float* __restrict__ q, const float* __restrict__ k,
                           const float* __restrict__ v,
                           const float* __restrict__ cache_k,
                           const float* __restrict__ cache_v,
                           const float* __restrict__ fc, const float* __restrict__ fs) {
    const float SC = 1.4426950408889634f * 0.125f;
    int idx = blockIdx.x * blockDim.x + threadIdx.x;
    if (idx < ROPE_ITEMS) {
        int c8 = (idx & 3) << 3;         // dim base: 0,8,16,24 (second item +32)
        int h  = (idx >> 2) & 15;
        int s  = idx >> 6;
        int pos = START_FRAME + s;
        int base = (s * H + h) * D + c8;
        const float* fcp = &fc[pos * 64 + c8];
        const float* fsp = &fs[pos * 64 + c8];

        uint4 qo0, qo1, ko0, ko1, vo0, vo1;
        // item A: dims [c8, c8+8)
        rope_pack8(&q[base], fcp, fsp, SC, qo0);
        rope_pack8(&k[base], fcp, fsp, 1.0f, ko0);
        conv_pack8(&v[base], vo0);
        // item B: dims [c8+32, c8+40)  (independent -> doubled MLP)
        rope_pack8(&q[base + 32], fcp + 32, fsp + 32, SC, qo1);
        rope_pack8(&k[base + 32], fcp + 32, fsp + 32, 1.0f, ko1);
        conv_pack8(&v[base + 32], vo1);

        size_t qdst = ((size_t)h * S + s) * D + c8;
        *(uint4*)&g_qh[qdst]      = qo0;
        *(uint4*)&g_qh[qdst + 32] = qo1;
        size_t dst = ((size_t)h * NKV + SPLIT + s) * D + c8;
        *(uint4*)&g_kh[dst]      = ko0;
        *(uint4*)&g_kh[dst + 32] = ko1;
        *(uint4*)&g_vh[dst]      = vo0;
        *(uint4*)&g_vh[dst + 32] = vo1;
    } else {
        int i4 = idx - ROPE_ITEMS;
        if (i4 >= CONV_ITEMS) return;
        int c8 = (i4 & 3) << 3;
        int h  = (i4 >> 2) & 15;
        int j  = i4 >> 6;
        size_t src = (size_t)(CACHE_OFF + j) * (H * D) + h * D + c8;
        uint4 ko0, ko1, vo0, vo1;
        conv_pack8(&cache_k[src], ko0);
        conv_pack8(&cache_k[src + 32], ko1);
        conv_pack8(&cache_v[src], vo0);
        conv_pack8(&cache_v[src + 32], vo1);
        size_t dst = ((size_t)h * NKV + j) * D + c8;
        *(uint4*)&g_kh[dst]      = ko0;
        *(uint4*)&g_kh[dst + 32] = ko1;
        *(uint4*)&g_vh[dst]      = vo0;
        *(uint4*)&g_vh[dst + 32] = vo1;
    }
}

// ---------------------------------------------------------------------------
// Flash attention (round-12 body, verbatim — proven 109.9us config):
// fp16 mma m16n8k16, ldmatrix B (+.trans V), 4-stage ring cp.async (depth-3),
// fused per-16-key block, ones-column L MMA, f16x2 softmax, async Q prologue.
// grid = (8, 16, 8) = 1024 CTAs, block = 128 (4 warps x 32 q-rows), 3 CTAs/SM.
// ---------------------------------------------------------------------------
__device__ __forceinline__ void prefetch_tile(uint32_t kbase, uint32_t vbase,
                                              int tid, int h, int kt) {
    const char* ksrc = (const char*)&g_kh[((size_t)h * NKV + (size_t)kt * BN) * D];
    const char* vsrc = (const char*)&g_vh[((size_t)h * NKV + (size_t)kt * BN) * D];
    #pragma unroll
    for (int g = 0; g < 4; g++) {
        int idx = tid + g * 128;
        int r = idx >> 3, c = idx & 7;
        uint32_t off = (uint32_t)(r * KS + c * 8) * 2;
        cp16(kbase + off, ksrc + (size_t)idx * 16);
        cp16(vbase + off, vsrc + (size_t)idx * 16);
    }
}

__global__ __launch_bounds__(128, 3) void attn_fp16() {
    extern __shared__ __align__(16) __half smem[];

    const int h     = blockIdx.y;
    const int q0    = blockIdx.x * BM;
    const int split = blockIdx.z;
    const int tid   = threadIdx.x;
    const int warp  = tid >> 5;
    const int lane  = tid & 31;
    const int gid   = lane >> 2;
    const int tig   = lane & 3;
    const int kt0   = split * TPT;

    const uint32_t sb = (uint32_t)__cvta_generic_to_shared(smem);
    uint32_t kaddr[4], vaddr[4];
    #pragma unroll
    for (int t = 0; t < 4; t++) {
        kaddr[t] = sb + (uint32_t)(t * STAGE_H) * 2u;
        vaddr[t] = kaddr[t] + (uint32_t)TILE_H * 2u;
    }

    const uint32_t loffB =
        (uint32_t)((((lane >> 4) & 1) * 8 + (lane & 7)) * KS * 2 + ((lane >> 3) & 1) * 16);
    const uint32_t loffA =
        (uint32_t)((lane & 15) * KS * 2 + ((lane >> 4) & 1) * 16);
    const uint32_t loffBV =
        (uint32_t)((((lane >> 3) & 1) * 8 + (lane & 7)) * KS * 2 + ((lane >> 4) & 1) * 16);
    const uint32_t loffLV =
        (uint32_t)((((lane >> 3) & 1) * 8 + (lane & 7)) * KS * 2 + 128);

    // prologue: async Q into stage 0 (halves 0-63 of 128 rows)
    {
        const char* qsrc = (const char*)&g_qh[((size_t)h * S + q0) * D];
        #pragma unroll
        for (int g = 0; g < 8; g++) {
            int idx = tid + g * 128;
            int r = idx >> 3, c = idx & 7;
            cp16(sb + (uint32_t)(r * KS + c * 8) * 2, qsrc + (size_t)idx * 16);
        }
        CP_COMMIT();
    }
    prefetch_tile(kaddr[1], vaddr[1], tid, h, kt0);     CP_COMMIT();
    prefetch_tile(kaddr[2], vaddr[2], tid, h, kt0 + 1); CP_COMMIT();
    prefetch_tile(kaddr[3], vaddr[3], tid, h, kt0 + 2); CP_COMMIT();

    // ones-column (dim 64) / zeros (65-71) in all 4 V areas
    {
        const __half one = __float2half(1.0f), zero = __float2half(0.0f);
        for (int i = tid; i < 4 * 64 * 8; i += 128) {
            int t = i >> 9, rem = i & 511;
            int key = rem >> 3, dd = 64 + (rem & 7);
            smem[t * STAGE_H + TILE_H + key * KS + dd] = (dd == 64) ? one : zero;
        }
    }

    CP_WAIT(3);
    __syncthreads();

    uint32_t qa[2][4][4];
    #pragma unroll
    for (int mt = 0; mt < 2; mt++) {
        uint32_t rowbase = sb + (uint32_t)((warp * 32 + mt * 16) * KS * 2) + loffA;
        #pragma unroll
        for (int kk = 0; kk < 4; kk++)
            ldsm_x4(rowbase + (uint32_t)(kk * 32),
                    qa[mt][kk][0], qa[mt][kk][1], qa[mt][kk][2], qa[mt][kk][3]);
    }

    float o[2][8][4];
    #pragma unroll
    for (int mt = 0; mt < 2; mt++)
        #pragma unroll
        for (int nn = 0; nn < 8; nn++)
            o[mt][nn][0] = o[mt][nn][1] = o[mt][nn][2] = o[mt][nn][3] = 0.f;
    float oL[2][4];
    #pragma unroll
    for (int mt = 0; mt < 2; mt++)
        oL[mt][0] = oL[mt][1] = oL[mt][2] = oL[mt][3] = 0.f;

    for (int j = 0; j < TPT; j++) {
        const int cs = (j + 1) & 3;

        if (j + 2 < TPT)      { CP_WAIT(2); }
        else if (j + 1 < TPT) { CP_WAIT(1); }
        else                  { CP_WAIT(0); }
        __syncthreads();

        if (j + 3 < TPT) {
            prefetch_tile(kaddr[j & 3], vaddr[j & 3], tid, h, kt0 + j + 3);
            CP_COMMIT();
        }

        // ---- fused per-16-key block: MMA1 -> softmax -> L + MMA2 ----
        #pragma unroll
        for (int kb = 0; kb < 4; kb++) {
            float sacc[2][2][4];
            #pragma unroll
            for (int mt = 0; mt < 2; mt++)
                #pragma unroll
                for (int nn = 0; nn < 2; nn++)
                    sacc[mt][nn][0] = sacc[mt][nn][1] = sacc[mt][nn][2] = sacc[mt][nn][3] = 0.f;
            #pragma unroll
            for (int kd = 0; kd < 4; kd++) {
                uint32_t b0, b1, b2, b3;
                ldsm_x4(kaddr[cs] + loffB + (uint32_t)(kb * 16 * KS * 2 + kd * 32),
                        b0, b1, b2, b3);
                mma_f16(sacc[0][0], qa[0][kd], b0, b1);
                mma_f16(sacc[0][1], qa[0][kd], b2, b3);
                mma_f16(sacc[1][0], qa[1][kd], b0, b1);
                mma_f16(sacc[1][1], qa[1][kd], b2, b3);
            }
            uint32_t pa[2][4];
            #pragma unroll
            for (int mt = 0; mt < 2; mt++) {
                pa[mt][0] = ex2_f16x2(cvt_f16x2(sacc[mt][0][1], sacc[mt][0][0]));
                pa[mt][1] = ex2_f16x2(cvt_f16x2(sacc[mt][0][3], sacc[mt][0][2]));
                pa[mt][2] = ex2_f16x2(cvt_f16x2(sacc[mt][1][1], sacc[mt][1][0]));
                pa[mt][3] = ex2_f16x2(cvt_f16x2(sacc[mt][1][3], sacc[mt][1][2]));
            }
            {
                uint32_t bL0, bL1;
                ldsm_x2_t(vaddr[cs] + loffLV + (uint32_t)(kb * 16 * KS * 2), bL0, bL1);
                mma_f16(oL[0], pa[0], bL0, bL1);
                mma_f16(oL[1], pa[1], bL0, bL1);
            }
            #pragma unroll
            for (int nnp = 0; nnp < 4; nnp++) {
                uint32_t b0, b1, b2, b3;
                ldsm_x4_t(vaddr[cs] + loffBV + (uint32_t)(kb * 16 * KS * 2 + nnp * 32),
                          b0, b1, b2, b3);
                mma_f16(o[0][2 * nnp],     pa[0], b0, b1);
                mma_f16(o[0][2 * nnp + 1], pa[0], b2, b3);
                mma_f16(o[1][2 * nnp],     pa[1], b0, b1);
                mma_f16(o[1][2 * nnp + 1], pa[1], b2, b3);
            }
        }
    }

    // epilogue: fp16 partial O via streaming stores, fp32 L
    #pragma unroll
    for (int mt = 0; mt < 2; mt++) {
        int r = q0 + warp * 32 + mt * 16 + gid;
        size_t b0 = ((size_t)split * S + r) * (H * D) + h * 64;
        size_t b1 = ((size_t)split * S + r + 8) * (H * D) + h * 64;
        #pragma unroll
        for (int nn = 0; nn < 8; nn++) {
            stg_cs_u32(&g_po[b0 + nn * 8 + 2 * tig], cvt_f16x2(o[mt][nn][1], o[mt][nn][0]));
            stg_cs_u32(&g_po[b1 + nn * 8 + 2 * tig], cvt_f16x2(o[mt][nn][3], o[mt][nn][2]));
        }
        if (tig == 0) {
            g_l[(size_t)split * (S * H) + (size_t)r * H + h]       = oL[mt][0];
            g_l[(size_t)split * (S * H) + (size_t)(r + 8) * H + h] = oL[mt][2];
        }
    }
}

// ---------------------------------------------------------------------------
// Merge splits: 4 outputs per thread (round-12 version, verbatim).
// ---------------------------------------------------------------------------
__global__ __launch_bounds__(256) void reduce_kernel(float* __restrict__ out) {
    int t = blockIdx.x * blockDim.x + threadIdx.x;   // S*H*D/4 threads
    if (t >= S * H * D / 4) return;
    int idx = t * 4;
    int h = (idx >> 6) & 15;
    int s = idx >> 10;
    int mlb = s * H + h;

    float den = 0.f;
    #pragma unroll
    for (int i = 0; i < NSPLIT; i++)
        den += g_l[(size_t)i * (S * H) + mlb];

    float acc0 = 0.f, acc1 = 0.f, acc2 = 0.f, acc3 = 0.f;
    #pragma unroll
    for (int i = 0; i < NSPLIT; i++) {
        uint2 pk = *(const uint2*)&g_po[(size_t)i * (S * H * D) + idx];
        float2 a0 = __half22float2(*(const __half2*)&pk.x);
        float2 a1 = __half22float2(*(const __half2*)&pk.y);
        acc0 += a0.x; acc1 += a0.y; acc2 += a1.x; acc3 += a1.y;
    }
    float r = 1.f / den;
    *(float4*)&out[idx] = make_float4(acc0 * r, acc1 * r, acc2 * r, acc3 * r);
}

// ---------------------------------------------------------------------------
extern "C" void kernel_launch(void* const* d_in, const int* in_sizes, int n_in,
                              void* d_out, int out_size) {
    const float* q  = (const float*)d_in[0];
    const float* k  = (const float*)d_in[1];
    const float* v  = (const float*)d_in[2];
    const float* ck = (const float*)d_in[3];
    const float* cv = (const float*)d_in[4];
    const float* fc = (const float*)d_in[5];
    const float* fs = (const float*)d_in[6];
    float* out = (float*)d_out;
    (void)in_sizes; (void)n_in; (void)out_size;

    int prep_items = ROPE_ITEMS + CONV_ITEMS;
    prep_fused<<<(prep_items + 255) / 256, 256>>>(q, k, v, ck, cv, fc, fs);

    cudaFuncSetAttribute(attn_fp16, cudaFuncAttributeMaxDynamicSharedMemorySize,
                         SM_HALVES * 2);
    dim3 grid(S / BM, H, NSPLIT);
    attn_fp16<<<grid, 128, SM_HALVES * 2>>>();

    reduce_kernel<<<(S * H * D / 4 + 255) / 256, 256>>>(out);
}